// round 3
// baseline (speedup 1.0000x reference)
#include <cuda_runtime.h>
#include <cstdint>

#define BB   256
#define LL   512
#define DD   64
#define NID  10000
#define MAXC 513                 // counts are 0..512 inclusive -> full coverage
#define TBLK 16                  // extra CTAs in kernel A that build the table

#define NROWS   (2 * BB * LL)    // 262144 output rows (src block then dst block)

// Scratch: packed per-position counts (lo16 = count in src seq, hi16 = in dst seq),
// laid out exactly like output rows: [0,BB*LL) = src positions, [BB*LL,..) = dst.
__device__ uint32_t cnt_buf[NROWS];
// Full lookup table g(a)[e], a in [0,513), stored as float4 rows of 16.
__device__ float4 g_table4[MAXC * 16];

// ---------------------------------------------------------------------------
// Kernel A: blocks [0,256) -> per-batch packed histogram + count scatter.
//           blocks [256,272) -> build the 513x64 table cooperatively.
// ---------------------------------------------------------------------------
__global__ void __launch_bounds__(512) counts_and_table(
        const int* __restrict__ src,
        const int* __restrict__ dst,
        const float* __restrict__ W1,
        const float* __restrict__ b1,
        const float* __restrict__ W2,
        const float* __restrict__ b2) {
    const int t = threadIdx.x;

    if (blockIdx.x >= BB) {
        // ---- table-builder role ----
        float* gt = (float*)g_table4;
        const int tb = blockIdx.x - BB;
        for (int idx = tb * 512 + t; idx < MAXC * DD; idx += TBLK * 512) {
            const int a = idx >> 6, e = idx & 63;
            float s = __ldg(&b2[e]);
            const float fa = (float)a;
            #pragma unroll 16
            for (int d = 0; d < DD; ++d) {
                float hv = fmaf(fa, __ldg(&W1[d]), __ldg(&b1[d]));
                hv = hv > 0.f ? hv : 0.f;
                s = fmaf(hv, __ldg(&W2[e * DD + d]), s);
            }
            gt[idx] = s;
        }
        return;
    }

    // ---- histogram role: one CTA per batch sample ----
    __shared__ uint32_t hist[NID];
    const int b = blockIdx.x;

    const uint4 z = make_uint4(0u, 0u, 0u, 0u);
    #pragma unroll
    for (int i = t; i < NID / 4; i += 512) ((uint4*)hist)[i] = z;

    const int sid = src[b * LL + t];
    const int did = dst[b * LL + t];
    __syncthreads();

    atomicAdd(&hist[sid], 1u);
    atomicAdd(&hist[did], 0x10000u);
    __syncthreads();

    // padding id 0 -> force (0,0) lookup (table row 0 after masking)
    cnt_buf[b * LL + t]           = sid ? hist[sid] : 0u;
    cnt_buf[BB * LL + b * LL + t] = did ? hist[did] : 0u;
}

// ---------------------------------------------------------------------------
// Kernel B: pure streaming encode. One float4 (16B of one output row) per
// thread-iteration; 4096 CTAs x 256 threads x 4 iters cover all 4.19M float4s.
// Table reads are L1-resident (few distinct count values); stores saturate L2.
// ---------------------------------------------------------------------------
__global__ void __launch_bounds__(256) encode_stream(float* __restrict__ out) {
    float4* __restrict__ o4 = (float4*)out;
    const float4* __restrict__ T4 = g_table4;

    size_t g4 = (size_t)blockIdx.x * 1024 + threadIdx.x;
    #pragma unroll
    for (int it = 0; it < 4; ++it, g4 += 256) {
        const uint32_t row  = (uint32_t)(g4 >> 4);
        const uint32_t lane = (uint32_t)(g4 & 15u);
        const uint32_t c = __ldg(&cnt_buf[row]);
        const float4 v0 = T4[(c & 0xFFFFu) * 16 + lane];
        const float4 v1 = T4[(c >> 16)     * 16 + lane];
        float4 w;
        w.x = v0.x + v1.x; w.y = v0.y + v1.y;
        w.z = v0.z + v1.z; w.w = v0.w + v1.w;
        o4[g4] = w;
    }
}

// ---------------------------------------------------------------------------
// Inputs: 0 src_ids, 1 dst_ids, 2 W1(D,1), 3 b1(D), 4 W2(D,D), 5 b2(D)
// Output: [src_feat | dst_feat], each B*L*D f32.
// ---------------------------------------------------------------------------
extern "C" void kernel_launch(void* const* d_in, const int* in_sizes, int n_in,
                              void* d_out, int out_size) {
    const int*   src = (const int*)d_in[0];
    const int*   dst = (const int*)d_in[1];
    const float* W1  = (const float*)d_in[2];
    const float* b1  = (const float*)d_in[3];
    const float* W2  = (const float*)d_in[4];
    const float* b2  = (const float*)d_in[5];
    float* out = (float*)d_out;

    counts_and_table<<<BB + TBLK, 512>>>(src, dst, W1, b1, W2, b2);
    encode_stream<<<4096, 256>>>(out);
}

// round 4
// speedup vs baseline: 3.3868x; 3.3868x over previous
#include <cuda_runtime.h>
#include <cstdint>

#define BB   256
#define LL   512
#define DD   64
#define NID  10000
#define MAXC 513                 // counts 0..512 inclusive -> full table coverage

#define NROWS (2 * BB * LL)      // 262144 output rows (src block then dst block)
#define TENT  (MAXC * DD)        // 32832 table entries
#define SLICE 129                // table entries per CTA: 256*129 = 33024 >= 32832

// Packed per-position counts (lo16 = count in src seq, hi16 = count in dst seq),
// laid out exactly like output rows.
__device__ uint32_t cnt_buf[NROWS];
// Full lookup table g(a)[e], a in [0,513).
__device__ float g_table[TENT];

// packed f32x2 add (Blackwell)
__device__ __forceinline__ long long addf32x2(long long a, long long b) {
    long long r;
    asm("add.rn.f32x2 %0, %1, %2;" : "=l"(r) : "l"(a), "l"(b));
    return r;
}

// ---------------------------------------------------------------------------
// Kernel A: one CTA per batch sample. Uniform code path for all CTAs:
// histogram + count scatter, plus a 129-entry slice of the g-table.
// ---------------------------------------------------------------------------
__global__ void __launch_bounds__(512) hist_counts(
        const int* __restrict__ src,
        const int* __restrict__ dst,
        const float* __restrict__ W1,
        const float* __restrict__ b1,
        const float* __restrict__ W2,
        const float* __restrict__ b2) {
    __shared__ uint32_t hist[NID];
    const int t = threadIdx.x;
    const int b = blockIdx.x;

    // zero histogram (128-bit stores), load ids
    const uint4 z = make_uint4(0u, 0u, 0u, 0u);
    for (int i = t; i < NID / 4; i += 512) ((uint4*)hist)[i] = z;
    const int sid = src[b * LL + t];
    const int did = dst[b * LL + t];
    __syncthreads();

    // packed dual histogram
    atomicAdd(&hist[sid], 1u);
    atomicAdd(&hist[did], 0x10000u);

    // table slice: threads [0,SLICE) each compute one entry while other warps
    // drain toward the barrier. Same path in every CTA (no role branching).
    if (t < SLICE) {
        const int idx = b * SLICE + t;
        if (idx < TENT) {
            const int a = idx >> 6, e = idx & 63;
            const float fa = (float)a;
            float s = __ldg(&b2[e]);
            const float* w2r = W2 + e * DD;
            #pragma unroll 8
            for (int d = 0; d < DD; ++d) {
                float hv = fmaf(fa, __ldg(&W1[d]), __ldg(&b1[d]));
                hv = hv > 0.f ? hv : 0.f;
                s = fmaf(hv, __ldg(&w2r[d]), s);
            }
            g_table[idx] = s;
        }
    }
    __syncthreads();

    // padding id 0 -> force (0,0) lookup
    cnt_buf[b * LL + t]           = sid ? hist[sid] : 0u;
    cnt_buf[BB * LL + b * LL + t] = did ? hist[did] : 0u;
}

// ---------------------------------------------------------------------------
// Kernel B: streaming encode. 4096 CTAs x 256 thr x 4 float4 per thread.
// Front-batched cnt loads, 8 independent table LDG.128s, packed f32x2 adds.
// ---------------------------------------------------------------------------
__global__ void __launch_bounds__(256) encode_stream(float* __restrict__ out) {
    const size_t base = (size_t)blockIdx.x * 1024 + threadIdx.x;
    const uint32_t lane = (uint32_t)(base & 15u);   // invariant across iters
    const longlong2* __restrict__ T2 = (const longlong2*)g_table;  // 16B chunks
    longlong2* __restrict__ o2 = (longlong2*)out;

    // front-batch the 4 count loads (rows stride 16 apart)
    uint32_t c[4];
    #pragma unroll
    for (int i = 0; i < 4; ++i)
        c[i] = __ldg(&cnt_buf[(base + 256u * i) >> 4]);

    // 8 independent table loads
    longlong2 v0[4], v1[4];
    #pragma unroll
    for (int i = 0; i < 4; ++i) {
        v0[i] = T2[(c[i] & 0xFFFFu) * 16 + lane];
        v1[i] = T2[(c[i] >> 16)     * 16 + lane];
    }

    // packed adds + stores
    #pragma unroll
    for (int i = 0; i < 4; ++i) {
        longlong2 w;
        w.x = addf32x2(v0[i].x, v1[i].x);
        w.y = addf32x2(v0[i].y, v1[i].y);
        o2[base + 256u * i] = w;
    }
}

// ---------------------------------------------------------------------------
// Inputs: 0 src_ids, 1 dst_ids, 2 W1(D,1), 3 b1(D), 4 W2(D,D), 5 b2(D)
// Output: [src_feat | dst_feat], each B*L*D f32.
// ---------------------------------------------------------------------------
extern "C" void kernel_launch(void* const* d_in, const int* in_sizes, int n_in,
                              void* d_out, int out_size) {
    const int*   src = (const int*)d_in[0];
    const int*   dst = (const int*)d_in[1];
    const float* W1  = (const float*)d_in[2];
    const float* b1  = (const float*)d_in[3];
    const float* W2  = (const float*)d_in[4];
    const float* b2  = (const float*)d_in[5];
    float* out = (float*)d_out;

    hist_counts<<<BB, 512>>>(src, dst, W1, b1, W2, b2);
    encode_stream<<<4096, 256>>>(out);
}